// round 7
// baseline (speedup 1.0000x reference)
#include <cuda_runtime.h>

// OBMC two-pass, channels-last + 5-group fusion.
// Pass 1: transpose x[B,C,H,W] -> xT[B,HW,C].
// Pass 2: one flow pixel -> all 5 group outputs (shared bilinear weights),
//         tap union = 12 float4 loads (vs 20 unfused). Warp = 2 pixels x
//         16 lanes (4 channels per lane). Outputs staged in smem, stored
//         as coalesced 16-px segments at shifted destinations.
// Borders: uncovered lines (g1 row255, g3 row0, g2 col255, g4 col0) are
// exact identity copies of x (OOB shift -> zero flow).

#define BB 4
#define CC 64
#define HH 256
#define WW 256
#define HW (HH * WW)
#define PXT 16

__device__ float g_xT[(size_t)BB * HW * CC];   // 67 MB scratch

// ---------------- Pass 1: transpose to channels-last ----------------
__global__ __launch_bounds__(256)
void obmc_transpose(const float* __restrict__ x) {
    __shared__ float t[32][33];
    const int b  = blockIdx.z;
    const int cb = blockIdx.y * 32;
    const int pb = blockIdx.x * 32;
    const int tx = threadIdx.x;
    const int ty = threadIdx.y;

    const float* xb = x + ((size_t)b * CC + cb) * HW + pb;
    #pragma unroll
    for (int i = 0; i < 32; i += 8)
        t[ty + i][tx] = xb[(size_t)(ty + i) * HW + tx];
    __syncthreads();

    float* o = g_xT + ((size_t)b * HW + pb) * CC + cb;
    #pragma unroll
    for (int i = 0; i < 32; i += 8)
        o[(size_t)(ty + i) * CC + tx] = t[tx][ty + i];
}

// ---------------- Pass 2: fused gather + store ----------------
__global__ __launch_bounds__(256, 3)
void obmc_gather(const float* __restrict__ flow, float* __restrict__ out) {
    __shared__ float st[5][PXT][65];   // stride 65: conflict-free read phase

    const int tid = threadIdx.x;
    const int l   = tid & 31;
    const int w   = tid >> 5;
    const int pxl = (w << 1) | (l >> 4);      // flow pixel 0..15 in block
    const int ch4 = l & 15;                   // 4-channel slice
    const int X0  = blockIdx.x * PXT;
    const int Y   = blockIdx.y;
    const int b   = blockIdx.z;
    const int xp  = X0 + pxl;
    const int pix = Y * WW + xp;

    const float* fb  = flow + (size_t)b * 2 * HW;
    const float* xTb = g_xT + (size_t)b * HW * CC;

    const float fx = __ldg(fb + pix);
    const float fy = __ldg(fb + HW + pix);

    const float gx = (float)xp + fx;
    const float gy = (float)Y  + fy;
    const float x0f = floorf(gx), y0f = floorf(gy);
    const float wx = gx - x0f,    wy = gy - y0f;
    const int x0 = (int)x0f, y0 = (int)y0f;

    // rows r0..r3 = y0-1..y0+2, cols c0..c3 = x0-1..x0+2 (clamped + validity)
    int rb_[4], cb_[4];
    float vr[4], vc[4];
    #pragma unroll
    for (int i = 0; i < 4; ++i) {
        const int r = y0 - 1 + i;
        vr[i] = ((unsigned)r < HH) ? 1.f : 0.f;
        rb_[i] = min(max(r, 0), HH - 1) * WW;
        const int c = x0 - 1 + i;
        vc[i] = ((unsigned)c < WW) ? 1.f : 0.f;
        cb_[i] = min(max(c, 0), WW - 1);
    }

    const float w00 = (1.f - wx) * (1.f - wy);
    const float w01 = wx * (1.f - wy);
    const float w10 = (1.f - wx) * wy;
    const float w11 = wx * wy;

    // 12 masked float4 taps
    #define TAP(nm, i, j) \
        float4 nm = __ldg((const float4*)(xTb + (size_t)(rb_[i] + cb_[j]) * CC) + ch4); \
        { const float m_ = vr[i] * vc[j]; nm.x *= m_; nm.y *= m_; nm.z *= m_; nm.w *= m_; }
    TAP(t10, 1, 0) TAP(t11, 1, 1) TAP(t12, 1, 2) TAP(t13, 1, 3)
    TAP(t20, 2, 0) TAP(t21, 2, 1) TAP(t22, 2, 2) TAP(t23, 2, 3)
    TAP(t01, 0, 1) TAP(t02, 0, 2) TAP(t31, 3, 1) TAP(t32, 3, 2)
    #undef TAP

    #define BLEND(dst, a, bq, cq, dq) \
        float4 dst; \
        dst.x = fmaf(w11, dq.x, fmaf(w10, cq.x, fmaf(w01, bq.x, w00 * a.x))); \
        dst.y = fmaf(w11, dq.y, fmaf(w10, cq.y, fmaf(w01, bq.y, w00 * a.y))); \
        dst.z = fmaf(w11, dq.z, fmaf(w10, cq.z, fmaf(w01, bq.z, w00 * a.z))); \
        dst.w = fmaf(w11, dq.w, fmaf(w10, cq.w, fmaf(w01, bq.w, w00 * a.w)));
    BLEND(v0, t11, t12, t21, t22)   // g0 @ (Y,   X)
    BLEND(v1, t01, t02, t11, t12)   // g1 @ (Y-1, X)
    BLEND(v3, t21, t22, t31, t32)   // g3 @ (Y+1, X)
    BLEND(v2, t10, t11, t20, t21)   // g2 @ (Y,   X-1)
    BLEND(v4, t12, t13, t22, t23)   // g4 @ (Y,   X+1)
    #undef BLEND

    {
        float* s;
        s = &st[0][pxl][ch4 * 4]; s[0]=v0.x; s[1]=v0.y; s[2]=v0.z; s[3]=v0.w;
        s = &st[1][pxl][ch4 * 4]; s[0]=v1.x; s[1]=v1.y; s[2]=v1.z; s[3]=v1.w;
        s = &st[2][pxl][ch4 * 4]; s[0]=v2.x; s[1]=v2.y; s[2]=v2.z; s[3]=v2.w;
        s = &st[3][pxl][ch4 * 4]; s[0]=v3.x; s[1]=v3.y; s[2]=v3.z; s[3]=v3.w;
        s = &st[4][pxl][ch4 * 4]; s[0]=v4.x; s[1]=v4.y; s[2]=v4.z; s[3]=v4.w;
    }

    // rare border identity copies (exact): center value = x at (Y,xp)
    if ((Y == 0) | (Y == HH - 1) | (xp == 0) | (xp == WW - 1)) {
        const float4 cv = __ldg((const float4*)(xTb + (size_t)pix * CC) + ch4);
        const float cvv[4] = {cv.x, cv.y, cv.z, cv.w};
        #pragma unroll
        for (int k = 0; k < 4; ++k) {
            const int c = ch4 * 4 + k;
            const size_t base = ((size_t)(b * 5) * CC + c) * HW + pix;
            if (Y == HH - 1)  __stcs(out + base + (size_t)1 * CC * HW, cvv[k]);
            if (Y == 0)       __stcs(out + base + (size_t)3 * CC * HW, cvv[k]);
            if (xp == WW - 1) __stcs(out + base + (size_t)2 * CC * HW, cvv[k]);
            if (xp == 0)      __stcs(out + base + (size_t)4 * CC * HW, cvv[k]);
        }
    }
    __syncthreads();

    // coalesced stores at shifted destinations
    const int px   = tid & 15;
    const int rsub = tid >> 4;                 // 0..15
    float* ob = out + (size_t)(b * 5) * CC * HW + (size_t)Y * WW + X0;
    #pragma unroll
    for (int i = 0; i < 20; ++i) {
        const int r = i * 16 + rsub;           // 0..319 (g*64 + c)
        const int g = r >> 6;
        const float v = st[g][px][r & 63];
        float* p = ob + (size_t)r * HW + px;
        bool ok = true;
        if (g == 1) { p -= WW; ok = (Y >= 1); }
        else if (g == 3) { p += WW; ok = (Y <= HH - 2); }
        else if (g == 2) { p -= 1;  ok = (X0 + px >= 1); }
        else if (g == 4) { p += 1;  ok = (X0 + px <= WW - 2); }
        if (ok) __stcs(p, v);
    }
}

extern "C" void kernel_launch(void* const* d_in, const int* in_sizes, int n_in,
                              void* d_out, int out_size) {
    const float* x    = (const float*)d_in[0];
    const float* flow = (const float*)d_in[1];
    float* out        = (float*)d_out;

    dim3 tgrid(HW / 32, CC / 32, BB);
    dim3 tblk(32, 8);
    obmc_transpose<<<tgrid, tblk>>>(x);

    dim3 ggrid(WW / PXT, HH, BB);   // 16 x 256 x 4
    obmc_gather<<<ggrid, 256>>>(flow, out);
}

// round 8
// speedup vs baseline: 1.0046x; 1.0046x over previous
#include <cuda_runtime.h>

// OBMC two-pass, channels-last + 5-group fusion.
// Pass 1: transpose x[B,C,H,W] -> xT[B,HW,C].
// Pass 2: one flow pixel -> all 5 group outputs (shared bilinear weights),
//         tap union = 12 float4 loads (vs 20 unfused). Warp = 2 pixels x
//         16 lanes (4 channels per lane). Outputs staged in smem, stored
//         as coalesced 16-px segments at shifted destinations.
// Borders: uncovered lines (g1 row255, g3 row0, g2 col255, g4 col0) are
// exact identity copies of x (OOB shift -> zero flow).

#define BB 4
#define CC 64
#define HH 256
#define WW 256
#define HW (HH * WW)
#define PXT 16

__device__ float g_xT[(size_t)BB * HW * CC];   // 67 MB scratch

// ---------------- Pass 1: transpose to channels-last ----------------
__global__ __launch_bounds__(256)
void obmc_transpose(const float* __restrict__ x) {
    __shared__ float t[32][33];
    const int b  = blockIdx.z;
    const int cb = blockIdx.y * 32;
    const int pb = blockIdx.x * 32;
    const int tx = threadIdx.x;
    const int ty = threadIdx.y;

    const float* xb = x + ((size_t)b * CC + cb) * HW + pb;
    #pragma unroll
    for (int i = 0; i < 32; i += 8)
        t[ty + i][tx] = xb[(size_t)(ty + i) * HW + tx];
    __syncthreads();

    float* o = g_xT + ((size_t)b * HW + pb) * CC + cb;
    #pragma unroll
    for (int i = 0; i < 32; i += 8)
        o[(size_t)(ty + i) * CC + tx] = t[tx][ty + i];
}

// ---------------- Pass 2: fused gather + store ----------------
__global__ __launch_bounds__(256, 3)
void obmc_gather(const float* __restrict__ flow, float* __restrict__ out) {
    __shared__ float st[5][PXT][65];   // stride 65: conflict-free read phase

    const int tid = threadIdx.x;
    const int l   = tid & 31;
    const int w   = tid >> 5;
    const int pxl = (w << 1) | (l >> 4);      // flow pixel 0..15 in block
    const int ch4 = l & 15;                   // 4-channel slice
    const int X0  = blockIdx.x * PXT;
    const int Y   = blockIdx.y;
    const int b   = blockIdx.z;
    const int xp  = X0 + pxl;
    const int pix = Y * WW + xp;

    const float* fb  = flow + (size_t)b * 2 * HW;
    const float* xTb = g_xT + (size_t)b * HW * CC;

    const float fx = __ldg(fb + pix);
    const float fy = __ldg(fb + HW + pix);

    const float gx = (float)xp + fx;
    const float gy = (float)Y  + fy;
    const float x0f = floorf(gx), y0f = floorf(gy);
    const float wx = gx - x0f,    wy = gy - y0f;
    const int x0 = (int)x0f, y0 = (int)y0f;

    // rows r0..r3 = y0-1..y0+2, cols c0..c3 = x0-1..x0+2 (clamped + validity)
    int rb_[4], cb_[4];
    float vr[4], vc[4];
    #pragma unroll
    for (int i = 0; i < 4; ++i) {
        const int r = y0 - 1 + i;
        vr[i] = ((unsigned)r < HH) ? 1.f : 0.f;
        rb_[i] = min(max(r, 0), HH - 1) * WW;
        const int c = x0 - 1 + i;
        vc[i] = ((unsigned)c < WW) ? 1.f : 0.f;
        cb_[i] = min(max(c, 0), WW - 1);
    }

    const float w00 = (1.f - wx) * (1.f - wy);
    const float w01 = wx * (1.f - wy);
    const float w10 = (1.f - wx) * wy;
    const float w11 = wx * wy;

    // 12 masked float4 taps
    #define TAP(nm, i, j) \
        float4 nm = __ldg((const float4*)(xTb + (size_t)(rb_[i] + cb_[j]) * CC) + ch4); \
        { const float m_ = vr[i] * vc[j]; nm.x *= m_; nm.y *= m_; nm.z *= m_; nm.w *= m_; }
    TAP(t10, 1, 0) TAP(t11, 1, 1) TAP(t12, 1, 2) TAP(t13, 1, 3)
    TAP(t20, 2, 0) TAP(t21, 2, 1) TAP(t22, 2, 2) TAP(t23, 2, 3)
    TAP(t01, 0, 1) TAP(t02, 0, 2) TAP(t31, 3, 1) TAP(t32, 3, 2)
    #undef TAP

    #define BLEND(dst, a, bq, cq, dq) \
        float4 dst; \
        dst.x = fmaf(w11, dq.x, fmaf(w10, cq.x, fmaf(w01, bq.x, w00 * a.x))); \
        dst.y = fmaf(w11, dq.y, fmaf(w10, cq.y, fmaf(w01, bq.y, w00 * a.y))); \
        dst.z = fmaf(w11, dq.z, fmaf(w10, cq.z, fmaf(w01, bq.z, w00 * a.z))); \
        dst.w = fmaf(w11, dq.w, fmaf(w10, cq.w, fmaf(w01, bq.w, w00 * a.w)));
    BLEND(v0, t11, t12, t21, t22)   // g0 @ (Y,   X)
    BLEND(v1, t01, t02, t11, t12)   // g1 @ (Y-1, X)
    BLEND(v3, t21, t22, t31, t32)   // g3 @ (Y+1, X)
    BLEND(v2, t10, t11, t20, t21)   // g2 @ (Y,   X-1)
    BLEND(v4, t12, t13, t22, t23)   // g4 @ (Y,   X+1)
    #undef BLEND

    {
        float* s;
        s = &st[0][pxl][ch4 * 4]; s[0]=v0.x; s[1]=v0.y; s[2]=v0.z; s[3]=v0.w;
        s = &st[1][pxl][ch4 * 4]; s[0]=v1.x; s[1]=v1.y; s[2]=v1.z; s[3]=v1.w;
        s = &st[2][pxl][ch4 * 4]; s[0]=v2.x; s[1]=v2.y; s[2]=v2.z; s[3]=v2.w;
        s = &st[3][pxl][ch4 * 4]; s[0]=v3.x; s[1]=v3.y; s[2]=v3.z; s[3]=v3.w;
        s = &st[4][pxl][ch4 * 4]; s[0]=v4.x; s[1]=v4.y; s[2]=v4.z; s[3]=v4.w;
    }

    // rare border identity copies (exact): center value = x at (Y,xp)
    if ((Y == 0) | (Y == HH - 1) | (xp == 0) | (xp == WW - 1)) {
        const float4 cv = __ldg((const float4*)(xTb + (size_t)pix * CC) + ch4);
        const float cvv[4] = {cv.x, cv.y, cv.z, cv.w};
        #pragma unroll
        for (int k = 0; k < 4; ++k) {
            const int c = ch4 * 4 + k;
            const size_t base = ((size_t)(b * 5) * CC + c) * HW + pix;
            if (Y == HH - 1)  __stcs(out + base + (size_t)1 * CC * HW, cvv[k]);
            if (Y == 0)       __stcs(out + base + (size_t)3 * CC * HW, cvv[k]);
            if (xp == WW - 1) __stcs(out + base + (size_t)2 * CC * HW, cvv[k]);
            if (xp == 0)      __stcs(out + base + (size_t)4 * CC * HW, cvv[k]);
        }
    }
    __syncthreads();

    // coalesced stores at shifted destinations
    const int px   = tid & 15;
    const int rsub = tid >> 4;                 // 0..15
    float* ob = out + (size_t)(b * 5) * CC * HW + (size_t)Y * WW + X0;
    #pragma unroll
    for (int i = 0; i < 20; ++i) {
        const int r = i * 16 + rsub;           // 0..319 (g*64 + c)
        const int g = r >> 6;
        const float v = st[g][px][r & 63];
        float* p = ob + (size_t)r * HW + px;
        bool ok = true;
        if (g == 1) { p -= WW; ok = (Y >= 1); }
        else if (g == 3) { p += WW; ok = (Y <= HH - 2); }
        else if (g == 2) { p -= 1;  ok = (X0 + px >= 1); }
        else if (g == 4) { p += 1;  ok = (X0 + px <= WW - 2); }
        if (ok) __stcs(p, v);
    }
}

extern "C" void kernel_launch(void* const* d_in, const int* in_sizes, int n_in,
                              void* d_out, int out_size) {
    const float* x    = (const float*)d_in[0];
    const float* flow = (const float*)d_in[1];
    float* out        = (float*)d_out;

    dim3 tgrid(HW / 32, CC / 32, BB);
    dim3 tblk(32, 8);
    obmc_transpose<<<tgrid, tblk>>>(x);

    dim3 ggrid(WW / PXT, HH, BB);   // 16 x 256 x 4
    obmc_gather<<<ggrid, 256>>>(flow, out);
}

// round 9
// speedup vs baseline: 1.0069x; 1.0023x over previous
#include <cuda_runtime.h>

// OBMC two-pass, channels-last + 5-group fusion.
// Pass 1: transpose x[B,C,H,W] -> xT[B,HW,C].
// Pass 2: one flow pixel -> all 5 group outputs (shared bilinear weights),
//         tap union = 12 float4 loads (vs 20 unfused). Warp = 2 pixels x
//         16 lanes (4 channels per lane). Outputs staged in smem, stored
//         as coalesced 16-px segments at shifted destinations.
// Borders: uncovered lines (g1 row255, g3 row0, g2 col255, g4 col0) are
// exact identity copies of x (OOB shift -> zero flow).

#define BB 4
#define CC 64
#define HH 256
#define WW 256
#define HW (HH * WW)
#define PXT 16

__device__ float g_xT[(size_t)BB * HW * CC];   // 67 MB scratch

// ---------------- Pass 1: transpose to channels-last ----------------
__global__ __launch_bounds__(256)
void obmc_transpose(const float* __restrict__ x) {
    __shared__ float t[32][33];
    const int b  = blockIdx.z;
    const int cb = blockIdx.y * 32;
    const int pb = blockIdx.x * 32;
    const int tx = threadIdx.x;
    const int ty = threadIdx.y;

    const float* xb = x + ((size_t)b * CC + cb) * HW + pb;
    #pragma unroll
    for (int i = 0; i < 32; i += 8)
        t[ty + i][tx] = xb[(size_t)(ty + i) * HW + tx];
    __syncthreads();

    float* o = g_xT + ((size_t)b * HW + pb) * CC + cb;
    #pragma unroll
    for (int i = 0; i < 32; i += 8)
        o[(size_t)(ty + i) * CC + tx] = t[tx][ty + i];
}

// ---------------- Pass 2: fused gather + store ----------------
__global__ __launch_bounds__(256, 3)
void obmc_gather(const float* __restrict__ flow, float* __restrict__ out) {
    __shared__ float st[5][PXT][65];   // stride 65: conflict-free read phase

    const int tid = threadIdx.x;
    const int l   = tid & 31;
    const int w   = tid >> 5;
    const int pxl = (w << 1) | (l >> 4);      // flow pixel 0..15 in block
    const int ch4 = l & 15;                   // 4-channel slice
    const int X0  = blockIdx.x * PXT;
    const int Y   = blockIdx.y;
    const int b   = blockIdx.z;
    const int xp  = X0 + pxl;
    const int pix = Y * WW + xp;

    const float* fb  = flow + (size_t)b * 2 * HW;
    const float* xTb = g_xT + (size_t)b * HW * CC;

    const float fx = __ldg(fb + pix);
    const float fy = __ldg(fb + HW + pix);

    const float gx = (float)xp + fx;
    const float gy = (float)Y  + fy;
    const float x0f = floorf(gx), y0f = floorf(gy);
    const float wx = gx - x0f,    wy = gy - y0f;
    const int x0 = (int)x0f, y0 = (int)y0f;

    // rows r0..r3 = y0-1..y0+2, cols c0..c3 = x0-1..x0+2 (clamped + validity)
    int rb_[4], cb_[4];
    float vr[4], vc[4];
    #pragma unroll
    for (int i = 0; i < 4; ++i) {
        const int r = y0 - 1 + i;
        vr[i] = ((unsigned)r < HH) ? 1.f : 0.f;
        rb_[i] = min(max(r, 0), HH - 1) * WW;
        const int c = x0 - 1 + i;
        vc[i] = ((unsigned)c < WW) ? 1.f : 0.f;
        cb_[i] = min(max(c, 0), WW - 1);
    }

    const float w00 = (1.f - wx) * (1.f - wy);
    const float w01 = wx * (1.f - wy);
    const float w10 = (1.f - wx) * wy;
    const float w11 = wx * wy;

    // 12 masked float4 taps
    #define TAP(nm, i, j) \
        float4 nm = __ldg((const float4*)(xTb + (size_t)(rb_[i] + cb_[j]) * CC) + ch4); \
        { const float m_ = vr[i] * vc[j]; nm.x *= m_; nm.y *= m_; nm.z *= m_; nm.w *= m_; }
    TAP(t10, 1, 0) TAP(t11, 1, 1) TAP(t12, 1, 2) TAP(t13, 1, 3)
    TAP(t20, 2, 0) TAP(t21, 2, 1) TAP(t22, 2, 2) TAP(t23, 2, 3)
    TAP(t01, 0, 1) TAP(t02, 0, 2) TAP(t31, 3, 1) TAP(t32, 3, 2)
    #undef TAP

    #define BLEND(dst, a, bq, cq, dq) \
        float4 dst; \
        dst.x = fmaf(w11, dq.x, fmaf(w10, cq.x, fmaf(w01, bq.x, w00 * a.x))); \
        dst.y = fmaf(w11, dq.y, fmaf(w10, cq.y, fmaf(w01, bq.y, w00 * a.y))); \
        dst.z = fmaf(w11, dq.z, fmaf(w10, cq.z, fmaf(w01, bq.z, w00 * a.z))); \
        dst.w = fmaf(w11, dq.w, fmaf(w10, cq.w, fmaf(w01, bq.w, w00 * a.w)));
    BLEND(v0, t11, t12, t21, t22)   // g0 @ (Y,   X)
    BLEND(v1, t01, t02, t11, t12)   // g1 @ (Y-1, X)
    BLEND(v3, t21, t22, t31, t32)   // g3 @ (Y+1, X)
    BLEND(v2, t10, t11, t20, t21)   // g2 @ (Y,   X-1)
    BLEND(v4, t12, t13, t22, t23)   // g4 @ (Y,   X+1)
    #undef BLEND

    {
        float* s;
        s = &st[0][pxl][ch4 * 4]; s[0]=v0.x; s[1]=v0.y; s[2]=v0.z; s[3]=v0.w;
        s = &st[1][pxl][ch4 * 4]; s[0]=v1.x; s[1]=v1.y; s[2]=v1.z; s[3]=v1.w;
        s = &st[2][pxl][ch4 * 4]; s[0]=v2.x; s[1]=v2.y; s[2]=v2.z; s[3]=v2.w;
        s = &st[3][pxl][ch4 * 4]; s[0]=v3.x; s[1]=v3.y; s[2]=v3.z; s[3]=v3.w;
        s = &st[4][pxl][ch4 * 4]; s[0]=v4.x; s[1]=v4.y; s[2]=v4.z; s[3]=v4.w;
    }

    // rare border identity copies (exact): center value = x at (Y,xp)
    if ((Y == 0) | (Y == HH - 1) | (xp == 0) | (xp == WW - 1)) {
        const float4 cv = __ldg((const float4*)(xTb + (size_t)pix * CC) + ch4);
        const float cvv[4] = {cv.x, cv.y, cv.z, cv.w};
        #pragma unroll
        for (int k = 0; k < 4; ++k) {
            const int c = ch4 * 4 + k;
            const size_t base = ((size_t)(b * 5) * CC + c) * HW + pix;
            if (Y == HH - 1)  __stcs(out + base + (size_t)1 * CC * HW, cvv[k]);
            if (Y == 0)       __stcs(out + base + (size_t)3 * CC * HW, cvv[k]);
            if (xp == WW - 1) __stcs(out + base + (size_t)2 * CC * HW, cvv[k]);
            if (xp == 0)      __stcs(out + base + (size_t)4 * CC * HW, cvv[k]);
        }
    }
    __syncthreads();

    // coalesced stores at shifted destinations
    const int px   = tid & 15;
    const int rsub = tid >> 4;                 // 0..15
    float* ob = out + (size_t)(b * 5) * CC * HW + (size_t)Y * WW + X0;
    #pragma unroll
    for (int i = 0; i < 20; ++i) {
        const int r = i * 16 + rsub;           // 0..319 (g*64 + c)
        const int g = r >> 6;
        const float v = st[g][px][r & 63];
        float* p = ob + (size_t)r * HW + px;
        bool ok = true;
        if (g == 1) { p -= WW; ok = (Y >= 1); }
        else if (g == 3) { p += WW; ok = (Y <= HH - 2); }
        else if (g == 2) { p -= 1;  ok = (X0 + px >= 1); }
        else if (g == 4) { p += 1;  ok = (X0 + px <= WW - 2); }
        if (ok) __stcs(p, v);
    }
}

extern "C" void kernel_launch(void* const* d_in, const int* in_sizes, int n_in,
                              void* d_out, int out_size) {
    const float* x    = (const float*)d_in[0];
    const float* flow = (const float*)d_in[1];
    float* out        = (float*)d_out;

    dim3 tgrid(HW / 32, CC / 32, BB);
    dim3 tblk(32, 8);
    obmc_transpose<<<tgrid, tblk>>>(x);

    dim3 ggrid(WW / PXT, HH, BB);   // 16 x 256 x 4
    obmc_gather<<<ggrid, 256>>>(flow, out);
}

// round 10
// speedup vs baseline: 1.0147x; 1.0078x over previous
#include <cuda_runtime.h>

// OBMC two-pass, channels-last + 5-group fusion + vectorized staging.
// Pass 1: transpose x[B,C,H,W] -> xT[B,HW,C].
// Pass 2: one flow pixel -> all 5 group outputs (shared bilinear weights,
//         12-tap float4 union). Staging smem is [g][px][68] (ch-contiguous,
//         16B aligned): write = 5 STS.128; g0/g1/g3 stores = STG.128 over
//         px-quads (aligned dests); g2/g4 (x-shift, misaligned) scalar.
// Borders: uncovered lines (g1 row255, g3 row0, g2 col255, g4 col0) are
// exact identity copies of x (OOB shift -> zero flow).

#define BB 4
#define CC 64
#define HH 256
#define WW 256
#define HW (HH * WW)
#define PXT 16

__device__ float g_xT[(size_t)BB * HW * CC];   // 67 MB scratch

// ---------------- Pass 1: transpose to channels-last ----------------
__global__ __launch_bounds__(256)
void obmc_transpose(const float* __restrict__ x) {
    __shared__ float t[32][33];
    const int b  = blockIdx.z;
    const int cb = blockIdx.y * 32;
    const int pb = blockIdx.x * 32;
    const int tx = threadIdx.x;
    const int ty = threadIdx.y;

    const float* xb = x + ((size_t)b * CC + cb) * HW + pb;
    #pragma unroll
    for (int i = 0; i < 32; i += 8)
        t[ty + i][tx] = xb[(size_t)(ty + i) * HW + tx];
    __syncthreads();

    float* o = g_xT + ((size_t)b * HW + pb) * CC + cb;
    #pragma unroll
    for (int i = 0; i < 32; i += 8)
        o[(size_t)(ty + i) * CC + tx] = t[tx][ty + i];
}

// ---------------- Pass 2: fused gather + vectorized store ----------------
__global__ __launch_bounds__(256, 3)
void obmc_gather(const float* __restrict__ flow, float* __restrict__ out) {
    __shared__ __align__(16) float st[5 * PXT * 68];   // [g][px][68]

    const int tid = threadIdx.x;
    const int l   = tid & 31;
    const int w   = tid >> 5;
    const int pxl = (w << 1) | (l >> 4);      // flow pixel 0..15 in block
    const int ch4 = l & 15;                   // 4-channel slice
    const int X0  = blockIdx.x * PXT;
    const int Y   = blockIdx.y;
    const int b   = blockIdx.z;
    const int xp  = X0 + pxl;
    const int pix = Y * WW + xp;

    const float* fb  = flow + (size_t)b * 2 * HW;
    const float* xTb = g_xT + (size_t)b * HW * CC;

    const float fx = __ldg(fb + pix);
    const float fy = __ldg(fb + HW + pix);

    const float gx = (float)xp + fx;
    const float gy = (float)Y  + fy;
    const float x0f = floorf(gx), y0f = floorf(gy);
    const float wx = gx - x0f,    wy = gy - y0f;
    const int x0 = (int)x0f, y0 = (int)y0f;

    // rows r0..r3 = y0-1..y0+2, cols c0..c3 = x0-1..x0+2 (clamped + validity)
    int rb_[4], cb_[4];
    float vr[4], vc[4];
    #pragma unroll
    for (int i = 0; i < 4; ++i) {
        const int r = y0 - 1 + i;
        vr[i] = ((unsigned)r < HH) ? 1.f : 0.f;
        rb_[i] = min(max(r, 0), HH - 1) * WW;
        const int c = x0 - 1 + i;
        vc[i] = ((unsigned)c < WW) ? 1.f : 0.f;
        cb_[i] = min(max(c, 0), WW - 1);
    }

    const float w00 = (1.f - wx) * (1.f - wy);
    const float w01 = wx * (1.f - wy);
    const float w10 = (1.f - wx) * wy;
    const float w11 = wx * wy;

    // 12 masked float4 taps
    #define TAP(nm, i, j) \
        float4 nm = __ldg((const float4*)(xTb + (size_t)(rb_[i] + cb_[j]) * CC) + ch4); \
        { const float m_ = vr[i] * vc[j]; nm.x *= m_; nm.y *= m_; nm.z *= m_; nm.w *= m_; }
    TAP(t10, 1, 0) TAP(t11, 1, 1) TAP(t12, 1, 2) TAP(t13, 1, 3)
    TAP(t20, 2, 0) TAP(t21, 2, 1) TAP(t22, 2, 2) TAP(t23, 2, 3)
    TAP(t01, 0, 1) TAP(t02, 0, 2) TAP(t31, 3, 1) TAP(t32, 3, 2)
    #undef TAP

    #define BLEND(dst, a, bq, cq, dq) \
        float4 dst; \
        dst.x = fmaf(w11, dq.x, fmaf(w10, cq.x, fmaf(w01, bq.x, w00 * a.x))); \
        dst.y = fmaf(w11, dq.y, fmaf(w10, cq.y, fmaf(w01, bq.y, w00 * a.y))); \
        dst.z = fmaf(w11, dq.z, fmaf(w10, cq.z, fmaf(w01, bq.z, w00 * a.z))); \
        dst.w = fmaf(w11, dq.w, fmaf(w10, cq.w, fmaf(w01, bq.w, w00 * a.w)));
    BLEND(v0, t11, t12, t21, t22)   // g0 @ (Y,   X)
    BLEND(v1, t01, t02, t11, t12)   // g1 @ (Y-1, X)
    BLEND(v2, t10, t11, t20, t21)   // g2 @ (Y,   X-1)
    BLEND(v3, t21, t22, t31, t32)   // g3 @ (Y+1, X)
    BLEND(v4, t12, t13, t22, t23)   // g4 @ (Y,   X+1)
    #undef BLEND

    // stage: 5 STS.128 (ch-contiguous, 16B aligned; 68 words/row)
    {
        float4* s4 = (float4*)st;                 // 17 float4 per px-row
        s4[(0 * PXT + pxl) * 17 + ch4] = v0;
        s4[(1 * PXT + pxl) * 17 + ch4] = v1;
        s4[(2 * PXT + pxl) * 17 + ch4] = v2;
        s4[(3 * PXT + pxl) * 17 + ch4] = v3;
        s4[(4 * PXT + pxl) * 17 + ch4] = v4;
    }

    // rare border identity copies (exact): center value = x at (Y,xp)
    if ((Y == 0) | (Y == HH - 1) | (xp == 0) | (xp == WW - 1)) {
        const float4 cv = __ldg((const float4*)(xTb + (size_t)pix * CC) + ch4);
        const float cvv[4] = {cv.x, cv.y, cv.z, cv.w};
        #pragma unroll
        for (int k = 0; k < 4; ++k) {
            const int c = ch4 * 4 + k;
            const size_t base = ((size_t)(b * 5) * CC + c) * HW + pix;
            if (Y == HH - 1)  __stcs(out + base + (size_t)1 * CC * HW, cvv[k]);
            if (Y == 0)       __stcs(out + base + (size_t)3 * CC * HW, cvv[k]);
            if (xp == WW - 1) __stcs(out + base + (size_t)2 * CC * HW, cvv[k]);
            if (xp == 0)      __stcs(out + base + (size_t)4 * CC * HW, cvv[k]);
        }
    }
    __syncthreads();

    float* ob = out + (size_t)(b * 5) * CC * HW + (size_t)Y * WW + X0;

    // vectorized stores: g0, g1, g3 (aligned destinations)
    {
        const int c   = tid >> 2;                 // channel 0..63
        const int px4 = tid & 3;                  // px quad 0..3
        #pragma unroll
        for (int vi = 0; vi < 3; ++vi) {
            const int sl = (vi == 2) ? 3 : vi;    // smem/out group slot
            const float* sb = st + (sl * PXT + px4 * 4) * 68 + c;
            float4 q;
            q.x = sb[0];
            q.y = sb[68];
            q.z = sb[136];
            q.w = sb[204];
            float* p = ob + (size_t)(sl * 64 + c) * HW + px4 * 4;
            bool ok = true;
            if (sl == 1)      { p -= WW; ok = (Y >= 1); }
            else if (sl == 3) { p += WW; ok = (Y <= HH - 2); }
            if (ok) __stcs((float4*)p, q);
        }
    }

    // scalar stores: g2 (x-1), g4 (x+1) — misaligned by 4B
    #pragma unroll
    for (int it = 0; it < 8; ++it) {
        const int idx = tid + it * 256;           // 0..2047
        const int px  = idx & 15;
        const int q   = idx >> 4;                 // 0..127
        const int sl  = (q < 64) ? 2 : 4;
        const int c   = q & 63;
        const float v = st[(sl * PXT + px) * 68 + c];
        float* p = ob + (size_t)(sl * 64 + c) * HW + px;
        bool ok;
        if (sl == 2) { p -= 1; ok = (X0 + px >= 1); }
        else         { p += 1; ok = (X0 + px <= WW - 2); }
        if (ok) __stcs(p, v);
    }
}

extern "C" void kernel_launch(void* const* d_in, const int* in_sizes, int n_in,
                              void* d_out, int out_size) {
    const float* x    = (const float*)d_in[0];
    const float* flow = (const float*)d_in[1];
    float* out        = (float*)d_out;

    dim3 tgrid(HW / 32, CC / 32, BB);
    dim3 tblk(32, 8);
    obmc_transpose<<<tgrid, tblk>>>(x);

    dim3 ggrid(WW / PXT, HH, BB);   // 16 x 256 x 4
    obmc_gather<<<ggrid, 256>>>(flow, out);
}

// round 11
// speedup vs baseline: 1.0640x; 1.0485x over previous
#include <cuda_runtime.h>

// OBMC two-pass, channels-last + 5-group fusion, occupancy-tuned.
// Pass 1: float4 transpose x[B,C,H,W] -> xT[B,HW,C].
// Pass 2: one flow pixel -> all 5 group outputs. 12-tap float4 union,
//         factorized masked weights (coeff = T[row]*L/R[col]) and two load
//         waves keep regs <= 64 so 4 CTAs/SM (occ ~50%) fit.
// Borders: uncovered lines (g1 row255, g3 row0, g2 col255, g4 col0) are
// exact identity copies of x (OOB shift -> zero flow).

#define BB 4
#define CC 64
#define HH 256
#define WW 256
#define HW (HH * WW)
#define PXT 16

__device__ float g_xT[(size_t)BB * HW * CC];   // 67 MB scratch

// ---------------- Pass 1: transpose to channels-last (float4) ----------------
__global__ __launch_bounds__(256)
void obmc_transpose(const float* __restrict__ x) {
    __shared__ float t[32][36];
    const int b   = blockIdx.z;
    const int cb  = blockIdx.y * 32;
    const int pb  = blockIdx.x * 32;
    const int tid = threadIdx.x;

    {   // load 32ch x 32px tile, float4 along px
        const int px4 = tid & 7;
        const int ch  = tid >> 3;
        const float4 v = __ldg((const float4*)(x + ((size_t)b * CC + cb + ch) * HW + pb) + px4);
        *(float4*)&t[ch][px4 * 4] = v;
    }
    __syncthreads();
    {   // store float4 along channels
        const int q  = tid & 7;        // channel quad
        const int px = tid >> 3;       // 0..31
        float4 v;
        v.x = t[q * 4 + 0][px];
        v.y = t[q * 4 + 1][px];
        v.z = t[q * 4 + 2][px];
        v.w = t[q * 4 + 3][px];
        *(float4*)(g_xT + ((size_t)b * HW + pb + px) * CC + cb + q * 4) = v;
    }
}

// ---------------- Pass 2: fused gather + vectorized store ----------------
__global__ __launch_bounds__(256, 4)
void obmc_gather(const float* __restrict__ flow, float* __restrict__ out) {
    __shared__ __align__(16) float st[5 * PXT * 68];   // [g][px][68]

    const int tid = threadIdx.x;
    const int l   = tid & 31;
    const int w   = tid >> 5;
    const int pxl = (w << 1) | (l >> 4);      // flow pixel 0..15 in block
    const int ch4 = l & 15;                   // 4-channel slice
    const int X0  = blockIdx.x * PXT;
    const int Y   = blockIdx.y;
    const int b   = blockIdx.z;
    const int xp  = X0 + pxl;
    const int pix = Y * WW + xp;

    const float* fb  = flow + (size_t)b * 2 * HW;
    const float* xTb = g_xT + (size_t)b * HW * CC;

    const float fx = __ldg(fb + pix);
    const float fy = __ldg(fb + HW + pix);

    const float gx = (float)xp + fx;
    const float gy = (float)Y  + fy;
    const float x0f = floorf(gx), y0f = floorf(gy);
    const float wx = gx - x0f,    wy = gy - y0f;
    const int x0 = (int)x0f, y0 = (int)y0f;

    // factorized masked weight tables; rows r=y0-1+i, cols c=x0-1+j
    int rb_[4], cb_[4];
    float Tw[4], Bw[4], Lw[4], Rw[4];
    #pragma unroll
    for (int i = 0; i < 4; ++i) {
        const int r = y0 - 1 + i;
        const float vr = ((unsigned)r < HH) ? 1.f : 0.f;
        rb_[i] = min(max(r, 0), HH - 1) * WW;
        Tw[i] = (1.f - wy) * vr;
        Bw[i] = wy * vr;
        const int c = x0 - 1 + i;
        const float vc = ((unsigned)c < WW) ? 1.f : 0.f;
        cb_[i] = min(max(c, 0), WW - 1);
        Lw[i] = (1.f - wx) * vc;
        Rw[i] = wx * vc;
    }

    #define LOADT(nm, i, j) \
        const float4 nm = __ldg((const float4*)(xTb + (size_t)(rb_[i] + cb_[j]) * CC) + ch4);
    #define BLEND4(dst, cA, tA, cB, tB, cC, tC, cD, tD) \
        float4 dst; \
        dst.x = fmaf(cD, tD.x, fmaf(cC, tC.x, fmaf(cB, tB.x, cA * tA.x))); \
        dst.y = fmaf(cD, tD.y, fmaf(cC, tC.y, fmaf(cB, tB.y, cA * tA.y))); \
        dst.z = fmaf(cD, tD.z, fmaf(cC, tC.z, fmaf(cB, tB.z, cA * tA.z))); \
        dst.w = fmaf(cD, tD.w, fmaf(cC, tC.w, fmaf(cB, tB.w, cA * tA.w)));

    float4* s4 = (float4*)st;                 // 17 float4 per px-row

    // ---- wave A: rows 1,2 (8 taps) -> v0, v2, v4 done; keep t11,t12,t21,t22 ----
    LOADT(t10, 1, 0) LOADT(t11, 1, 1) LOADT(t12, 1, 2) LOADT(t13, 1, 3)
    LOADT(t20, 2, 0) LOADT(t21, 2, 1) LOADT(t22, 2, 2) LOADT(t23, 2, 3)

    BLEND4(v0, Tw[1]*Lw[1], t11, Tw[1]*Rw[2], t12, Bw[2]*Lw[1], t21, Bw[2]*Rw[2], t22)
    s4[(0 * PXT + pxl) * 17 + ch4] = v0;
    BLEND4(v2, Tw[1]*Lw[0], t10, Tw[1]*Rw[1], t11, Bw[2]*Lw[0], t20, Bw[2]*Rw[1], t21)
    s4[(2 * PXT + pxl) * 17 + ch4] = v2;
    BLEND4(v4, Tw[1]*Lw[2], t12, Tw[1]*Rw[3], t13, Bw[2]*Lw[2], t22, Bw[2]*Rw[3], t23)
    s4[(4 * PXT + pxl) * 17 + ch4] = v4;

    // ---- wave B: rows 0,3 (4 taps) -> v1, v3 ----
    LOADT(t01, 0, 1) LOADT(t02, 0, 2) LOADT(t31, 3, 1) LOADT(t32, 3, 2)

    BLEND4(v1, Tw[0]*Lw[1], t01, Tw[0]*Rw[2], t02, Bw[1]*Lw[1], t11, Bw[1]*Rw[2], t12)
    s4[(1 * PXT + pxl) * 17 + ch4] = v1;
    BLEND4(v3, Tw[2]*Lw[1], t21, Tw[2]*Rw[2], t22, Bw[3]*Lw[1], t31, Bw[3]*Rw[2], t32)
    s4[(3 * PXT + pxl) * 17 + ch4] = v3;

    #undef LOADT
    #undef BLEND4

    // rare border identity copies (exact): center value = x at (Y,xp)
    if ((Y == 0) | (Y == HH - 1) | (xp == 0) | (xp == WW - 1)) {
        const float4 cv = __ldg((const float4*)(xTb + (size_t)pix * CC) + ch4);
        const float cvv[4] = {cv.x, cv.y, cv.z, cv.w};
        #pragma unroll
        for (int k = 0; k < 4; ++k) {
            const int c = ch4 * 4 + k;
            const size_t base = ((size_t)(b * 5) * CC + c) * HW + pix;
            if (Y == HH - 1)  __stcs(out + base + (size_t)1 * CC * HW, cvv[k]);
            if (Y == 0)       __stcs(out + base + (size_t)3 * CC * HW, cvv[k]);
            if (xp == WW - 1) __stcs(out + base + (size_t)2 * CC * HW, cvv[k]);
            if (xp == 0)      __stcs(out + base + (size_t)4 * CC * HW, cvv[k]);
        }
    }
    __syncthreads();

    float* ob = out + (size_t)(b * 5) * CC * HW + (size_t)Y * WW + X0;

    // vectorized stores: g0, g1, g3 (aligned destinations)
    {
        const int c   = tid >> 2;                 // channel 0..63
        const int px4 = tid & 3;                  // px quad 0..3
        #pragma unroll
        for (int vi = 0; vi < 3; ++vi) {
            const int sl = (vi == 2) ? 3 : vi;
            const float* sb = st + (sl * PXT + px4 * 4) * 68 + c;
            float4 q;
            q.x = sb[0];
            q.y = sb[68];
            q.z = sb[136];
            q.w = sb[204];
            float* p = ob + (size_t)(sl * 64 + c) * HW + px4 * 4;
            bool ok = true;
            if (sl == 1)      { p -= WW; ok = (Y >= 1); }
            else if (sl == 3) { p += WW; ok = (Y <= HH - 2); }
            if (ok) __stcs((float4*)p, q);
        }
    }

    // scalar stores: g2 (x-1), g4 (x+1) — misaligned by 4B
    #pragma unroll
    for (int it = 0; it < 8; ++it) {
        const int idx = tid + it * 256;           // 0..2047
        const int px  = idx & 15;
        const int q   = idx >> 4;                 // 0..127
        const int sl  = (q < 64) ? 2 : 4;
        const int c   = q & 63;
        const float v = st[(sl * PXT + px) * 68 + c];
        float* p = ob + (size_t)(sl * 64 + c) * HW + px;
        bool ok;
        if (sl == 2) { p -= 1; ok = (X0 + px >= 1); }
        else         { p += 1; ok = (X0 + px <= WW - 2); }
        if (ok) __stcs(p, v);
    }
}

extern "C" void kernel_launch(void* const* d_in, const int* in_sizes, int n_in,
                              void* d_out, int out_size) {
    const float* x    = (const float*)d_in[0];
    const float* flow = (const float*)d_in[1];
    float* out        = (float*)d_out;

    dim3 tgrid(HW / 32, CC / 32, BB);
    dim3 tblk(256);
    obmc_transpose<<<tgrid, tblk>>>(x);

    dim3 ggrid(WW / PXT, HH, BB);   // 16 x 256 x 4
    obmc_gather<<<ggrid, 256>>>(flow, out);
}